// round 2
// baseline (speedup 1.0000x reference)
#include <cuda_runtime.h>

#define Bn 2048
#define Tn 512
#define Hn 16
#define Ln 8
#define WPB 7
#define NBLK 296   // 2 blocks per SM on 148 SMs

typedef unsigned long long ull;

// Ping-pong scratch for inter-layer hidden sequences (64 MB each).
__device__ float g_bufA[(size_t)Bn * Tn * Hn];
__device__ float g_bufB[(size_t)Bn * Tn * Hn];

// ---- packed fp32x2 FMA (Blackwell): d = a * b + d ----
__device__ __forceinline__ void ffma2(ull& d, ull a, ull b) {
    asm("fma.rn.f32x2 %0, %1, %2, %0;" : "+l"(d) : "l"(a), "l"(b));
}
__device__ __forceinline__ float2 u2f(ull a) {
    float2 f;
    asm("mov.b64 {%0,%1}, %2;" : "=f"(f.x), "=f"(f.y) : "l"(a));
    return f;
}
__device__ __forceinline__ ull pack2(float x, float y) {
    ull r;
    asm("mov.b64 %0, {%1,%2};" : "=l"(r) : "f"(x), "f"(y));
    return r;
}
// Load 16 contiguous floats as 8 packed f32x2 (4x 128-bit loads).
__device__ __forceinline__ void load8(ull* d, const float* p) {
    const ulonglong2* q = (const ulonglong2*)p;
    ulonglong2 v0 = q[0], v1 = q[1], v2 = q[2], v3 = q[3];
    d[0] = v0.x; d[1] = v0.y; d[2] = v1.x; d[3] = v1.y;
    d[4] = v2.x; d[5] = v2.y; d[6] = v3.x; d[7] = v3.y;
}
__device__ __forceinline__ float ex2f(float x) {
    float r; asm("ex2.approx.f32 %0, %1;" : "=f"(r) : "f"(x)); return r;
}
__device__ __forceinline__ float rcpf(float x) {
    float r; asm("rcp.approx.f32 %0, %1;" : "=f"(r) : "f"(x)); return r;
}

#define L2E 1.4426950408889634f

// One LSTM layer. Warp = ONE batch element.
// Lanes 0-15: gate rows i_j (row j)    and g_j (row 32+j)
// Lanes 16-31: gate rows f_j (row 16+j) and o_j (row 48+j)
// Weights live in registers as packed f32x2 over K. h exchanged via smem.
__global__ void __launch_bounds__(224, 2)
lstm_layer(const float* __restrict__ in, float* __restrict__ out,
           const float* __restrict__ Wih, const float* __restrict__ Whh,
           const float* __restrict__ bih, const float* __restrict__ bhh,
           int write_all)
{
    __shared__ __align__(16) float sh[WPB][2][16];

    const int warp = threadIdx.x >> 5;
    const int lane = threadIdx.x & 31;
    const int b = blockIdx.x * WPB + warp;
    if (b >= Bn) return;

    const int j   = lane & 15;
    const bool lo = lane < 16;
    const int r0  = lane;        // i | f rows
    const int r1  = lane + 32;   // g | o rows

    // weights -> registers (packed pairs over K)
    ull wx0[8], wh0[8], wx1[8], wh1[8];
    load8(wx0, Wih + r0 * Hn);  load8(wh0, Whh + r0 * Hn);
    load8(wx1, Wih + r1 * Hn);  load8(wh1, Whh + r1 * Hn);
    const ull bias0 = pack2(bih[r0] + bhh[r0], 0.0f);
    const ull bias1 = pack2(bih[r1] + bhh[r1], 0.0f);

    // paired-activation constants for pass B: tanh(g) | sigmoid(o)
    const float mB = lo ? (-2.0f * L2E) : (-1.0f * L2E);
    const float pB = lo ? 2.0f : 1.0f;
    const float qB = lo ? -1.0f : 0.0f;

    sh[warp][0][j] = 0.0f;
    float c = 0.0f;
    __syncwarp();

    const float* xptr = in + (size_t)b * Tn * Hn;
    float*       orow = out + (size_t)b * Tn * Hn;

    ull xp[8];
    load8(xp, xptr);   // prefetch t = 0

#pragma unroll 2
    for (int t = 0; t < Tn; t++) {
        // prefetch next x (clamped at tail)
        ull xn[8];
        const int tnext = (t + 1 < Tn) ? (t + 1) : t;
        load8(xn, xptr + tnext * Hn);

        // previous h (broadcast from smem, 4x LDS.128)
        ull hp[8];
        load8(hp, &sh[warp][t & 1][0]);

        ull a0 = bias0, a1 = bias1;
#pragma unroll
        for (int i = 0; i < 8; i++) { ffma2(a0, wx0[i], xp[i]); ffma2(a1, wx1[i], xp[i]); }
#pragma unroll
        for (int i = 0; i < 8; i++) { ffma2(a0, wh0[i], hp[i]); ffma2(a1, wh1[i], hp[i]); }
        float2 f0 = u2f(a0), f1 = u2f(a1);
        const float va = f0.x + f0.y;   // gate i | f
        const float vb = f1.x + f1.y;   // gate g | o

        // pass A: sigmoid(i) | sigmoid(f)
        const float sa = rcpf(1.0f + ex2f(va * (-L2E)));
        // pass B: tanh(g) | sigmoid(o)
        const float rb = rcpf(1.0f + ex2f(vb * mB));
        const float tb = fmaf(pB, rb, qB);

        // cross-half exchange: lo sends sig(i)*tanh(g), hi sends sig(f)
        const float v   = lo ? (sa * tb) : sa;
        const float x16 = __shfl_xor_sync(0xffffffffu, v, 16);

        // hi lanes: c = sig(f)*c + sig(i)*tanh(g); h = sig(o)*tanh(c)
        c = fmaf(sa, c, x16);                       // garbage on lo lanes (never used)
        const float rc = rcpf(1.0f + ex2f(c * (-2.0f * L2E)));
        const float th = fmaf(2.0f, rc, -1.0f);
        const float h  = tb * th;

        if (!lo) {
            sh[warp][(t + 1) & 1][j] = h;
            if (write_all || t == Tn - 1) orow[t * Hn + j] = h;
        }
        __syncwarp();

#pragma unroll
        for (int i = 0; i < 8; i++) xp[i] = xn[i];
    }
}

// Readout: position = last @ Wp^T + bp ; orientation = tanh(last @ Wo^T + bo)
__global__ void head_kernel(const float* __restrict__ hbuf,
                            const float* __restrict__ Wp, const float* __restrict__ bp,
                            const float* __restrict__ Wo, const float* __restrict__ bo,
                            float* __restrict__ out)
{
    int b = blockIdx.x * blockDim.x + threadIdx.x;
    if (b >= Bn) return;
    const float* h = hbuf + (size_t)b * Tn * Hn + (size_t)(Tn - 1) * Hn;
    float hv[16];
#pragma unroll
    for (int i = 0; i < 16; i++) hv[i] = h[i];

#pragma unroll
    for (int r = 0; r < 3; r++) {
        float s = bp[r];
#pragma unroll
        for (int k = 0; k < 16; k++) s += hv[k] * Wp[r * 16 + k];
        out[b * 6 + r] = s;
    }
#pragma unroll
    for (int r = 0; r < 3; r++) {
        float s = bo[r];
#pragma unroll
        for (int k = 0; k < 16; k++) s += hv[k] * Wo[r * 16 + k];
        float th = 2.0f * rcpf(1.0f + ex2f(s * (-2.0f * L2E))) - 1.0f;
        out[b * 6 + 3 + r] = th;
    }
}

extern "C" void kernel_launch(void* const* d_in, const int* in_sizes, int n_in,
                              void* d_out, int out_size)
{
    const float* x   = (const float*)d_in[0];
    const float* Wih = (const float*)d_in[1];
    const float* Whh = (const float*)d_in[2];
    const float* bih = (const float*)d_in[3];
    const float* bhh = (const float*)d_in[4];
    const float* Wp  = (const float*)d_in[5];
    const float* bp  = (const float*)d_in[6];
    const float* Wo  = (const float*)d_in[7];
    const float* bo  = (const float*)d_in[8];
    float* out = (float*)d_out;

    float *bufA, *bufB;
    cudaGetSymbolAddress((void**)&bufA, g_bufA);
    cudaGetSymbolAddress((void**)&bufB, g_bufB);

    const float* cur = x;
    for (int l = 0; l < Ln; l++) {
        float* o = (l & 1) ? bufB : bufA;
        int write_all = (l != Ln - 1);
        lstm_layer<<<NBLK, 224>>>(cur, o,
                                  Wih + (size_t)l * 64 * Hn,
                                  Whh + (size_t)l * 64 * Hn,
                                  bih + (size_t)l * 64,
                                  bhh + (size_t)l * 64,
                                  write_all);
        cur = o;
    }
    head_kernel<<<(Bn + 255) / 256, 256>>>(cur, Wp, bp, Wo, bo, out);
}

// round 3
// speedup vs baseline: 1.0303x; 1.0303x over previous
#include <cuda_runtime.h>

#define Bn 2048
#define Tn 512
#define Hn 16
#define Ln 8
#define WPB 7
#define NBLK 296   // 296 x 7 warps = 2072 >= 2048; exactly 2 CTAs/SM

typedef unsigned long long ull;

// Ping-pong scratch for inter-layer hidden sequences (64 MB each).
__device__ float g_bufA[(size_t)Bn * Tn * Hn];
__device__ float g_bufB[(size_t)Bn * Tn * Hn];

// ---- packed fp32x2 FMA (Blackwell): d = a * b + d ----
__device__ __forceinline__ void ffma2(ull& d, ull a, ull b) {
    asm("fma.rn.f32x2 %0, %1, %2, %0;" : "+l"(d) : "l"(a), "l"(b));
}
__device__ __forceinline__ float2 u2f(ull a) {
    float2 f;
    asm("mov.b64 {%0,%1}, %2;" : "=f"(f.x), "=f"(f.y) : "l"(a));
    return f;
}
__device__ __forceinline__ ull pack2(float x, float y) {
    ull r;
    asm("mov.b64 %0, {%1,%2};" : "=l"(r) : "f"(x), "f"(y));
    return r;
}
// Load 16 contiguous floats as 8 packed f32x2 (4x 128-bit loads).
__device__ __forceinline__ void load8(ull* d, const float* p) {
    const ulonglong2* q = (const ulonglong2*)p;
    ulonglong2 v0 = q[0], v1 = q[1], v2 = q[2], v3 = q[3];
    d[0] = v0.x; d[1] = v0.y; d[2] = v1.x; d[3] = v1.y;
    d[4] = v2.x; d[5] = v2.y; d[6] = v3.x; d[7] = v3.y;
}
// HW tanh (MUFU.TANH, sm_75+): 1 MUFU op.
__device__ __forceinline__ float tanha(float x) {
    float r; asm("tanh.approx.f32 %0, %1;" : "=f"(r) : "f"(x)); return r;
}

// One LSTM layer. Warp = ONE batch element.
// Lanes 0-15 : rows (j, 32+j)   -> gates (i, g)
// Lanes 16-31: rows (16+j,48+j) -> gates (f, o)
// Weights live in registers as packed f32x2 over K. h broadcast via smem.
__global__ void __launch_bounds__(224, 2)
lstm_layer(const float* __restrict__ in, float* __restrict__ out,
           const float* __restrict__ Wih, const float* __restrict__ Whh,
           const float* __restrict__ bih, const float* __restrict__ bhh,
           int write_all)
{
    __shared__ __align__(16) float sh[WPB][2][16];

    const int warp = threadIdx.x >> 5;
    const int lane = threadIdx.x & 31;
    const int b = blockIdx.x * WPB + warp;
    if (b >= Bn) return;

    const int j   = lane & 15;
    const bool lo = lane < 16;
    const int r0  = lane;        // i | f rows
    const int r1  = lane + 32;   // g | o rows

    // weights -> registers (packed pairs over K)
    ull wx0[8], wh0[8], wx1[8], wh1[8];
    load8(wx0, Wih + r0 * Hn);  load8(wh0, Whh + r0 * Hn);
    load8(wx1, Wih + r1 * Hn);  load8(wh1, Whh + r1 * Hn);
    const ull bias0 = pack2(bih[r0] + bhh[r0], 0.0f);
    const ull bias1 = pack2(bih[r1] + bhh[r1], 0.0f);

    // pass-B activation constants: lo = tanh(g), hi = sigmoid(o)
    const float mB = lo ? 1.0f : 0.5f;
    const float pB = lo ? 1.0f : 0.5f;
    const float qB = lo ? 0.0f : 0.5f;

    sh[warp][0][j] = 0.0f;
    float c = 0.0f;
    __syncwarp();

    const float* xptr = in + (size_t)b * Tn * Hn;
    float*       orow = out + (size_t)b * Tn * Hn;

    ull xp[8];
    load8(xp, xptr);   // prefetch t = 0

#pragma unroll 2
    for (int t = 0; t < Tn; t++) {
        // h broadcast first: it's the critical input
        ull hp[8];
        load8(hp, &sh[warp][t & 1][0]);

        // prefetch next x (clamped at tail) — independent of everything
        ull xn[8];
        const int tnext = (t + 1 < Tn) ? (t + 1) : t;
        load8(xn, xptr + tnext * Hn);

        // x-projection: independent of h, issues under the LDS shadow
        ull ax0 = bias0, ax1 = bias1;
#pragma unroll
        for (int i = 0; i < 8; i++) { ffma2(ax0, wx0[i], xp[i]); ffma2(ax1, wx1[i], xp[i]); }
        // h-projection: 8-deep chain per accumulator
        ull ah0 = 0ULL, ah1 = 0ULL;
#pragma unroll
        for (int i = 0; i < 8; i++) { ffma2(ah0, wh0[i], hp[i]); ffma2(ah1, wh1[i], hp[i]); }

        float2 A0 = u2f(ax0), A1 = u2f(ax1), H0 = u2f(ah0), H1 = u2f(ah1);
        const float va = (A0.x + A0.y) + (H0.x + H0.y);   // gate i | f
        const float vb = (A1.x + A1.y) + (H1.x + H1.y);   // gate g | o

        // pass A: sigmoid(i) | sigmoid(f)  (one MUFU.TANH + FMA)
        const float tA = fmaf(0.5f, tanha(0.5f * va), 0.5f);
        // pass B: tanh(g) | sigmoid(o)     (one MUFU.TANH + FMA, per-lane consts)
        const float tB = fmaf(pB, tanha(mB * vb), qB);

        // lo sends sig(i)*tanh(g); hi sends sig(f) (unused by lo)
        const float v   = lo ? (tA * tB) : tA;
        const float x16 = __shfl_xor_sync(0xffffffffu, v, 16);

        // hi lanes: c = sig(f)*c + sig(i)*tanh(g); h = sig(o)*tanh(c)
        c = fmaf(tA, c, x16);            // garbage on lo lanes (never used)
        const float h = tB * tanha(c);

        if (!lo) {
            sh[warp][(t + 1) & 1][j] = h;
            if (write_all || t == Tn - 1) orow[t * Hn + j] = h;
        }
        __syncwarp();

#pragma unroll
        for (int i = 0; i < 8; i++) xp[i] = xn[i];
    }
}

// Readout: position = last @ Wp^T + bp ; orientation = tanh(last @ Wo^T + bo)
__global__ void head_kernel(const float* __restrict__ hbuf,
                            const float* __restrict__ Wp, const float* __restrict__ bp,
                            const float* __restrict__ Wo, const float* __restrict__ bo,
                            float* __restrict__ out)
{
    int b = blockIdx.x * blockDim.x + threadIdx.x;
    if (b >= Bn) return;
    const float* h = hbuf + (size_t)b * Tn * Hn + (size_t)(Tn - 1) * Hn;
    float hv[16];
#pragma unroll
    for (int i = 0; i < 16; i++) hv[i] = h[i];

#pragma unroll
    for (int r = 0; r < 3; r++) {
        float s = bp[r];
#pragma unroll
        for (int k = 0; k < 16; k++) s += hv[k] * Wp[r * 16 + k];
        out[b * 6 + r] = s;
    }
#pragma unroll
    for (int r = 0; r < 3; r++) {
        float s = bo[r];
#pragma unroll
        for (int k = 0; k < 16; k++) s += hv[k] * Wo[r * 16 + k];
        out[b * 6 + 3 + r] = tanha(s);
    }
}

extern "C" void kernel_launch(void* const* d_in, const int* in_sizes, int n_in,
                              void* d_out, int out_size)
{
    const float* x   = (const float*)d_in[0];
    const float* Wih = (const float*)d_in[1];
    const float* Whh = (const float*)d_in[2];
    const float* bih = (const float*)d_in[3];
    const float* bhh = (const float*)d_in[4];
    const float* Wp  = (const float*)d_in[5];
    const float* bp  = (const float*)d_in[6];
    const float* Wo  = (const float*)d_in[7];
    const float* bo  = (const float*)d_in[8];
    float* out = (float*)d_out;

    float *bufA, *bufB;
    cudaGetSymbolAddress((void**)&bufA, g_bufA);
    cudaGetSymbolAddress((void**)&bufB, g_bufB);

    const float* cur = x;
    for (int l = 0; l < Ln; l++) {
        float* o = (l & 1) ? bufB : bufA;
        int write_all = (l != Ln - 1);
        lstm_layer<<<NBLK, 224>>>(cur, o,
                                  Wih + (size_t)l * 64 * Hn,
                                  Whh + (size_t)l * 64 * Hn,
                                  bih + (size_t)l * 64,
                                  bhh + (size_t)l * 64,
                                  write_all);
        cur = o;
    }
    head_kernel<<<(Bn + 255) / 256, 256>>>(cur, Wp, bp, Wo, bo, out);
}

// round 5
// speedup vs baseline: 1.4945x; 1.4505x over previous
#include <cuda_runtime.h>
#include <cstdint>

#define Bn 2048
#define Tn 512
#define Hn 16
#define Ln 8
#define WPB 7
#define NBLK ((Bn + WPB - 1) / WPB)   // 293 CTAs, 2/SM -> 1 wave
#define CHUNK 16
#define NCHUNK (Tn / CHUNK)

typedef unsigned long long ull;
typedef unsigned int u32;

// Ping-pong scratch for inter-layer hidden sequences (64 MB each).
__device__ float g_bufA[(size_t)Bn * Tn * Hn];
__device__ float g_bufB[(size_t)Bn * Tn * Hn];

// ---- packed fp32x2 ops (Blackwell) ----
__device__ __forceinline__ void ffma2(ull& d, ull a, ull b) {
    asm("fma.rn.f32x2 %0, %1, %2, %0;" : "+l"(d) : "l"(a), "l"(b));
}
__device__ __forceinline__ ull fadd2(ull a, ull b) {
    ull r; asm("add.rn.f32x2 %0, %1, %2;" : "=l"(r) : "l"(a), "l"(b)); return r;
}
__device__ __forceinline__ float2 u2f(ull a) {
    float2 f;
    asm("mov.b64 {%0,%1}, %2;" : "=f"(f.x), "=f"(f.y) : "l"(a));
    return f;
}
__device__ __forceinline__ ull pack2(float x, float y) {
    ull r;
    asm("mov.b64 %0, {%1,%2};" : "=l"(r) : "f"(x), "f"(y));
    return r;
}
// Load 16 contiguous floats as 8 packed f32x2 (4x LDS.128/LDG.128).
__device__ __forceinline__ void load8(ull* d, const float* p) {
    const ulonglong2* q = (const ulonglong2*)p;
    ulonglong2 v0 = q[0], v1 = q[1], v2 = q[2], v3 = q[3];
    d[0] = v0.x; d[1] = v0.y; d[2] = v1.x; d[3] = v1.y;
    d[4] = v2.x; d[5] = v2.y; d[6] = v3.x; d[7] = v3.y;
}
__device__ __forceinline__ float tanha(float x) {
    float r; asm("tanh.approx.f32 %0, %1;" : "=f"(r) : "f"(x)); return r;
}
// Predicated global store — single @p STG, no BSSY/BSYNC.
__device__ __forceinline__ void st_pred(float* addr, float v, int pred) {
    asm volatile("{ .reg .pred p; setp.ne.s32 p, %0, 0; @p st.global.f32 [%1], %2; }"
                 :: "r"(pred), "l"(addr), "f"(v));
}
__device__ __forceinline__ void cp16(u32 saddr, const float* g) {
    asm volatile("cp.async.cg.shared.global [%0], [%1], 16;" :: "r"(saddr), "l"(g));
}
__device__ __forceinline__ void cp_commit() { asm volatile("cp.async.commit_group;"); }
__device__ __forceinline__ void cp_wait0()  { asm volatile("cp.async.wait_group 0;"); }

// One LSTM layer. Warp = ONE batch element.
// Lanes 0-15 : rows (j, 32+j)   -> gates (i, g)
// Lanes 16-31: rows (16+j,48+j) -> gates (f, o)
// Weights in registers (f32x2). h via smem. x staged via cp.async chunks.
__global__ void __launch_bounds__(224, 2)
lstm_layer(const float* __restrict__ in, float* __restrict__ out,
           const float* __restrict__ Wih, const float* __restrict__ Whh,
           const float* __restrict__ bih, const float* __restrict__ bhh,
           int write_all)
{
    __shared__ __align__(16) float sh[WPB][2][32];            // h exchange (lo half scratch)
    __shared__ __align__(16) float xs[WPB][2][CHUNK][Hn];     // x staging, double buffered

    const int warp = threadIdx.x >> 5;
    const int lane = threadIdx.x & 31;
    const int b = blockIdx.x * WPB + warp;
    if (b >= Bn) return;

    const int j   = lane & 15;
    const bool lo = lane < 16;
    const int r0  = lane;        // i | f rows
    const int r1  = lane + 32;   // g | o rows

    ull wx0[8], wh0[8], wx1[8], wh1[8];
    load8(wx0, Wih + r0 * Hn);  load8(wh0, Whh + r0 * Hn);
    load8(wx1, Wih + r1 * Hn);  load8(wh1, Whh + r1 * Hn);
    const ull bias0 = pack2(bih[r0] + bhh[r0], 0.0f);
    const ull bias1 = pack2(bih[r1] + bhh[r1], 0.0f);

    // pass-B constants: lo = tanh(g), hi = sigmoid(o)
    const float mB = lo ? 1.0f : 0.5f;
    const float pB = lo ? 1.0f : 0.5f;
    const float qB = lo ? 0.0f : 0.5f;

    sh[warp][0][lane] = 0.0f;
    float c = 0.0f;

    const float* xptr = in + (size_t)b * Tn * Hn;
    float*       orow = out + (size_t)b * Tn * Hn;

    // prefetch chunk 0 into buffer 0 (2 x 16B per lane = 1 KB per warp)
    {
        u32 s0 = (u32)__cvta_generic_to_shared(&xs[warp][0][0][0]);
        cp16(s0 + lane * 16,             xptr + lane * 4);
        cp16(s0 + (lane + 32) * 16,      xptr + (lane + 32) * 4);
        cp_commit();
    }
    __syncwarp();

    for (int ch = 0; ch < NCHUNK; ch++) {
        const int cur = ch & 1;
        cp_wait0();          // chunk ch is resident in xs[warp][cur]
        __syncwarp();

        // prefetch chunk ch+1 into the other buffer (clamped; harmless refetch at tail)
        {
            const int nch = (ch + 1 < NCHUNK) ? ch + 1 : ch;
            const float* g = xptr + nch * (CHUNK * Hn);
            u32 s0 = (u32)__cvta_generic_to_shared(&xs[warp][cur ^ 1][0][0]);
            cp16(s0 + lane * 16,        g + lane * 4);
            cp16(s0 + (lane + 32) * 16, g + (lane + 32) * 4);
            cp_commit();
        }

#pragma unroll
        for (int s = 0; s < CHUNK; s++) {
            const int t = ch * CHUNK + s;

            ull hp[8];
            load8(hp, &sh[warp][s & 1][16]);          // h broadcast (t&1 == s&1)
            ull xv[8];
            load8(xv, &xs[warp][cur][s][0]);          // x broadcast from smem

            ull a0 = bias0, a1 = bias1, h0 = 0ULL, h1 = 0ULL;
#pragma unroll
            for (int i = 0; i < 8; i++) { ffma2(a0, wx0[i], xv[i]); ffma2(a1, wx1[i], xv[i]); }
#pragma unroll
            for (int i = 0; i < 8; i++) { ffma2(h0, wh0[i], hp[i]); ffma2(h1, wh1[i], hp[i]); }
            a0 = fadd2(a0, h0);
            a1 = fadd2(a1, h1);
            float2 A0 = u2f(a0), A1 = u2f(a1);
            const float va = A0.x + A0.y;   // gate i | f
            const float vb = A1.x + A1.y;   // gate g | o

            const float tA = fmaf(0.5f, tanha(0.5f * va), 0.5f);   // sig(i) | sig(f)
            const float tB = fmaf(pB, tanha(mB * vb), qB);         // tanh(g) | sig(o)

            const float v   = lo ? (tA * tB) : tA;
            const float x16 = __shfl_xor_sync(0xffffffffu, v, 16);

            c = fmaf(tA, c, x16);              // valid on hi lanes only
            const float h = tB * tanha(c);

            sh[warp][(s + 1) & 1][lane] = h;   // unconditional STS (lo half = scratch)
            st_pred(orow + t * Hn + j, h,
                    (!lo) && (write_all || t == Tn - 1));
            __syncwarp();
        }
    }
}

// Readout: position = last @ Wp^T + bp ; orientation = tanh(last @ Wo^T + bo)
__global__ void head_kernel(const float* __restrict__ hbuf,
                            const float* __restrict__ Wp, const float* __restrict__ bp,
                            const float* __restrict__ Wo, const float* __restrict__ bo,
                            float* __restrict__ out)
{
    int b = blockIdx.x * blockDim.x + threadIdx.x;
    if (b >= Bn) return;
    const float* h = hbuf + (size_t)b * Tn * Hn + (size_t)(Tn - 1) * Hn;
    float hv[16];
#pragma unroll
    for (int i = 0; i < 16; i++) hv[i] = h[i];

#pragma unroll
    for (int r = 0; r < 3; r++) {
        float s = bp[r];
#pragma unroll
        for (int k = 0; k < 16; k++) s += hv[k] * Wp[r * 16 + k];
        out[b * 6 + r] = s;
    }
#pragma unroll
    for (int r = 0; r < 3; r++) {
        float s = bo[r];
#pragma unroll
        for (int k = 0; k < 16; k++) s += hv[k] * Wo[r * 16 + k];
        out[b * 6 + 3 + r] = tanha(s);
    }
}

extern "C" void kernel_launch(void* const* d_in, const int* in_sizes, int n_in,
                              void* d_out, int out_size)
{
    const float* x   = (const float*)d_in[0];
    const float* Wih = (const float*)d_in[1];
    const float* Whh = (const float*)d_in[2];
    const float* bih = (const float*)d_in[3];
    const float* bhh = (const float*)d_in[4];
    const float* Wp  = (const float*)d_in[5];
    const float* bp  = (const float*)d_in[6];
    const float* Wo  = (const float*)d_in[7];
    const float* bo  = (const float*)d_in[8];
    float* out = (float*)d_out;

    float *bufA, *bufB;
    cudaGetSymbolAddress((void**)&bufA, g_bufA);
    cudaGetSymbolAddress((void**)&bufB, g_bufB);

    const float* cur = x;
    for (int l = 0; l < Ln; l++) {
        float* o = (l & 1) ? bufB : bufA;
        int write_all = (l != Ln - 1);
        lstm_layer<<<NBLK, 224>>>(cur, o,
                                  Wih + (size_t)l * 64 * Hn,
                                  Whh + (size_t)l * 64 * Hn,
                                  bih + (size_t)l * 64,
                                  bhh + (size_t)l * 64,
                                  write_all);
        cur = o;
    }
    head_kernel<<<(Bn + 255) / 256, 256>>>(cur, Wp, bp, Wo, bo, out);
}

// round 6
// speedup vs baseline: 1.6193x; 1.0835x over previous
#include <cuda_runtime.h>
#include <cstdint>

#define Bn 2048
#define Tn 512
#define Hn 16
#define Ln 8
#define WPB 7                          // warps per CTA
#define BPC (WPB * 2)                  // 14 batches per CTA
#define NBLK ((Bn + BPC - 1) / BPC)    // 147 CTAs -> 1 per SM
#define CHUNK 16
#define NCHUNK (Tn / CHUNK)

typedef unsigned long long ull;
typedef unsigned int u32;

// Ping-pong scratch for inter-layer hidden sequences (64 MB each).
__device__ float g_bufA[(size_t)Bn * Tn * Hn];
__device__ float g_bufB[(size_t)Bn * Tn * Hn];

// ---- packed fp32x2 ops (Blackwell) ----
__device__ __forceinline__ void ffma2(ull& d, ull a, ull b) {
    asm("fma.rn.f32x2 %0, %1, %2, %0;" : "+l"(d) : "l"(a), "l"(b));
}
__device__ __forceinline__ ull fmul2(ull a, ull b) {
    ull r; asm("mul.rn.f32x2 %0, %1, %2;" : "=l"(r) : "l"(a), "l"(b)); return r;
}
__device__ __forceinline__ float2 u2f(ull a) {
    float2 f;
    asm("mov.b64 {%0,%1}, %2;" : "=f"(f.x), "=f"(f.y) : "l"(a));
    return f;
}
__device__ __forceinline__ ull pack2(float x, float y) {
    ull r;
    asm("mov.b64 %0, {%1,%2};" : "=l"(r) : "f"(x), "f"(y));
    return r;
}
// Load 16 contiguous floats as 8 packed f32x2 (4x 128-bit loads).
__device__ __forceinline__ void load8(ull* d, const float* p) {
    const ulonglong2* q = (const ulonglong2*)p;
    ulonglong2 v0 = q[0], v1 = q[1], v2 = q[2], v3 = q[3];
    d[0] = v0.x; d[1] = v0.y; d[2] = v1.x; d[3] = v1.y;
    d[4] = v2.x; d[5] = v2.y; d[6] = v3.x; d[7] = v3.y;
}
__device__ __forceinline__ float tanha(float x) {
    float r; asm("tanh.approx.f32 %0, %1;" : "=f"(r) : "f"(x)); return r;
}
// Predicated global store — single @p STG, no BSSY/BSYNC.
__device__ __forceinline__ void st_pred(float* addr, float v, int pred) {
    asm volatile("{ .reg .pred p; setp.ne.s32 p, %0, 0; @p st.global.f32 [%1], %2; }"
                 :: "r"(pred), "l"(addr), "f"(v));
}
__device__ __forceinline__ void cp16(u32 saddr, const float* g) {
    asm volatile("cp.async.cg.shared.global [%0], [%1], 16;" :: "r"(saddr), "l"(g));
}
__device__ __forceinline__ void cp_commit() { asm volatile("cp.async.commit_group;"); }
__device__ __forceinline__ void cp_wait0()  { asm volatile("cp.async.wait_group 0;"); }

// One LSTM layer. Warp = TWO batch elements (lanes 0-15 / 16-31).
// Lane (half, j) owns hidden unit j of its batch: gate rows j, 16+j, 32+j, 48+j.
// No cross-lane gate exchange. Weights in registers (f32x2, sigmoid rows
// pre-scaled by 0.5 so sigma(v) = 0.5*tanh(acc)+0.5). h via smem broadcast.
// x staged through smem via cp.async in 16-step chunks.
__global__ void __launch_bounds__(224, 1)
lstm_layer(const float* __restrict__ in, float* __restrict__ out,
           const float* __restrict__ Wih, const float* __restrict__ Whh,
           const float* __restrict__ bih, const float* __restrict__ bhh,
           int write_all)
{
    __shared__ __align__(16) float sh[WPB][2][2][Hn];            // [warp][parity][half][j]
    __shared__ __align__(16) float xs[WPB][2][2][CHUNK][Hn];     // [warp][buf][half][step][j]

    const int warp = threadIdx.x >> 5;
    const int lane = threadIdx.x & 31;
    const int half = lane >> 4;
    const int j    = lane & 15;
    const int b    = blockIdx.x * BPC + warp * 2 + half;
    if (b >= Bn) return;   // whole warp exits together (batch pairs aligned)

    // ---- weights -> registers; sigmoid-gate rows scaled by 0.5 ----
    ull wx[4][8], wh[4][8], bias[4];
    const ull halfpack = pack2(0.5f, 0.5f);
#pragma unroll
    for (int q = 0; q < 4; q++) {
        const int row = q * Hn + j;          // q: 0=i 1=f 2=g 3=o
        load8(wx[q], Wih + row * Hn);
        load8(wh[q], Whh + row * Hn);
        float bb = bih[row] + bhh[row];
        if (q != 2) {                        // sigmoid gates: fold the 1/2
            bb *= 0.5f;
#pragma unroll
            for (int i = 0; i < 8; i++) {
                wx[q][i] = fmul2(wx[q][i], halfpack);
                wh[q][i] = fmul2(wh[q][i], halfpack);
            }
        }
        bias[q] = pack2(bb, 0.0f);
    }

    sh[warp][0][half][j] = 0.0f;
    float c = 0.0f;

    const float* xptr = in + (size_t)b * Tn * Hn;
    float*       orow = out + (size_t)b * Tn * Hn;

    // prefetch chunk 0 into buffer 0 (per half: 1 KB contiguous; 4 cp16/lane)
    {
        u32 s0 = (u32)__cvta_generic_to_shared(&xs[warp][0][half][0][0]);
#pragma unroll
        for (int k = 0; k < 4; k++)
            cp16(s0 + (k * 16 + j) * 16, xptr + (k * 16 + j) * 4);
        cp_commit();
    }
    __syncwarp();

    for (int ch = 0; ch < NCHUNK; ch++) {
        const int cur = ch & 1;
        cp_wait0();
        __syncwarp();

        // prefetch chunk ch+1 (clamped refetch at tail — harmless)
        {
            const int nch = (ch + 1 < NCHUNK) ? ch + 1 : ch;
            const float* g = xptr + nch * (CHUNK * Hn);
            u32 s0 = (u32)__cvta_generic_to_shared(&xs[warp][cur ^ 1][half][0][0]);
#pragma unroll
            for (int k = 0; k < 4; k++)
                cp16(s0 + (k * 16 + j) * 16, g + (k * 16 + j) * 4);
            cp_commit();
        }

#pragma unroll 4
        for (int s = 0; s < CHUNK; s++) {
            const int t = ch * CHUNK + s;

            ull hp[8], xv[8];
            load8(hp, &sh[warp][s & 1][half][0]);      // h broadcast (16 lanes/addr)
            load8(xv, &xs[warp][cur][half][s][0]);     // x broadcast

            ull a0 = bias[0], a1 = bias[1], a2 = bias[2], a3 = bias[3];
#pragma unroll
            for (int i = 0; i < 8; i++) {
                ffma2(a0, wx[0][i], xv[i]); ffma2(a1, wx[1][i], xv[i]);
                ffma2(a2, wx[2][i], xv[i]); ffma2(a3, wx[3][i], xv[i]);
            }
#pragma unroll
            for (int i = 0; i < 8; i++) {
                ffma2(a0, wh[0][i], hp[i]); ffma2(a1, wh[1][i], hp[i]);
                ffma2(a2, wh[2][i], hp[i]); ffma2(a3, wh[3][i], hp[i]);
            }
            float2 F0 = u2f(a0), F1 = u2f(a1), F2 = u2f(a2), F3 = u2f(a3);
            const float vi = F0.x + F0.y;   // pre-halved
            const float vf = F1.x + F1.y;   // pre-halved
            const float vg = F2.x + F2.y;
            const float vo = F3.x + F3.y;   // pre-halved

            const float si = fmaf(0.5f, tanha(vi), 0.5f);
            const float sf = fmaf(0.5f, tanha(vf), 0.5f);
            const float tg = tanha(vg);
            const float so = fmaf(0.5f, tanha(vo), 0.5f);

            c = fmaf(sf, c, si * tg);
            const float h = so * tanha(c);

            sh[warp][(s + 1) & 1][half][j] = h;
            st_pred(orow + t * Hn + j, h, write_all | (t == Tn - 1));
            __syncwarp();
        }
    }
}

// Readout: position = last @ Wp^T + bp ; orientation = tanh(last @ Wo^T + bo)
__global__ void head_kernel(const float* __restrict__ hbuf,
                            const float* __restrict__ Wp, const float* __restrict__ bp,
                            const float* __restrict__ Wo, const float* __restrict__ bo,
                            float* __restrict__ out)
{
    int b = blockIdx.x * blockDim.x + threadIdx.x;
    if (b >= Bn) return;
    const float* h = hbuf + (size_t)b * Tn * Hn + (size_t)(Tn - 1) * Hn;
    float hv[16];
#pragma unroll
    for (int i = 0; i < 16; i++) hv[i] = h[i];

#pragma unroll
    for (int r = 0; r < 3; r++) {
        float s = bp[r];
#pragma unroll
        for (int k = 0; k < 16; k++) s += hv[k] * Wp[r * 16 + k];
        out[b * 6 + r] = s;
    }
#pragma unroll
    for (int r = 0; r < 3; r++) {
        float s = bo[r];
#pragma unroll
        for (int k = 0; k < 16; k++) s += hv[k] * Wo[r * 16 + k];
        out[b * 6 + 3 + r] = tanha(s);
    }
}

extern "C" void kernel_launch(void* const* d_in, const int* in_sizes, int n_in,
                              void* d_out, int out_size)
{
    const float* x   = (const float*)d_in[0];
    const float* Wih = (const float*)d_in[1];
    const float* Whh = (const float*)d_in[2];
    const float* bih = (const float*)d_in[3];
    const float* bhh = (const float*)d_in[4];
    const float* Wp  = (const float*)d_in[5];
    const float* bp  = (const float*)d_in[6];
    const float* Wo  = (const float*)d_in[7];
    const float* bo  = (const float*)d_in[8];
    float* out = (float*)d_out;

    float *bufA, *bufB;
    cudaGetSymbolAddress((void**)&bufA, g_bufA);
    cudaGetSymbolAddress((void**)&bufB, g_bufB);

    const float* cur = x;
    for (int l = 0; l < Ln; l++) {
        float* o = (l & 1) ? bufB : bufA;
        int write_all = (l != Ln - 1);
        lstm_layer<<<NBLK, 224>>>(cur, o,
                                  Wih + (size_t)l * 64 * Hn,
                                  Whh + (size_t)l * 64 * Hn,
                                  bih + (size_t)l * 64,
                                  bhh + (size_t)l * 64,
                                  write_all);
        cur = o;
    }
    head_kernel<<<(Bn + 255) / 256, 256>>>(cur, Wp, bp, Wo, bo, out);
}

// round 7
// speedup vs baseline: 1.7274x; 1.0667x over previous
#include <cuda_runtime.h>
#include <cstdint>

#define Bn 2048
#define Tn 512
#define Hn 16
#define Ln 8
#define WPB 7                          // warps per CTA
#define BPC (WPB * 2)                  // 14 batches per CTA
#define NBLK ((Bn + BPC - 1) / BPC)    // 147 CTAs -> 1 per SM
#define CHUNK 16
#define NCHUNK (Tn / CHUNK)

typedef unsigned long long ull;
typedef unsigned int u32;

// Ping-pong scratch for inter-layer hidden sequences (64 MB each).
__device__ float g_bufA[(size_t)Bn * Tn * Hn];
__device__ float g_bufB[(size_t)Bn * Tn * Hn];

// ---- packed fp32x2 ops (Blackwell) ----
__device__ __forceinline__ void ffma2(ull& d, ull a, ull b) {
    asm("fma.rn.f32x2 %0, %1, %2, %0;" : "+l"(d) : "l"(a), "l"(b));
}
__device__ __forceinline__ ull fmul2(ull a, ull b) {
    ull r; asm("mul.rn.f32x2 %0, %1, %2;" : "=l"(r) : "l"(a), "l"(b)); return r;
}
__device__ __forceinline__ float2 u2f(ull a) {
    float2 f;
    asm("mov.b64 {%0,%1}, %2;" : "=f"(f.x), "=f"(f.y) : "l"(a));
    return f;
}
__device__ __forceinline__ ull pack2(float x, float y) {
    ull r;
    asm("mov.b64 %0, {%1,%2};" : "=l"(r) : "f"(x), "f"(y));
    return r;
}
// Load 16 contiguous floats as 8 packed f32x2 (4x 128-bit loads).
__device__ __forceinline__ void load8(ull* d, const float* p) {
    const ulonglong2* q = (const ulonglong2*)p;
    ulonglong2 v0 = q[0], v1 = q[1], v2 = q[2], v3 = q[3];
    d[0] = v0.x; d[1] = v0.y; d[2] = v1.x; d[3] = v1.y;
    d[4] = v2.x; d[5] = v2.y; d[6] = v3.x; d[7] = v3.y;
}
__device__ __forceinline__ float tanha(float x) {
    float r; asm("tanh.approx.f32 %0, %1;" : "=f"(r) : "f"(x)); return r;
}
__device__ __forceinline__ void cp16(u32 saddr, const float* g) {
    asm volatile("cp.async.cg.shared.global [%0], [%1], 16;" :: "r"(saddr), "l"(g));
}
__device__ __forceinline__ void cp_commit() { asm volatile("cp.async.commit_group;"); }
__device__ __forceinline__ void cp_wait0()  { asm volatile("cp.async.wait_group 0;"); }

// One LSTM layer. Warp = TWO batch elements (lanes 0-15 / 16-31).
// Lane (half, j) owns hidden unit j of its batch: gate rows j, 16+j, 32+j, 48+j.
// Weights in registers (f32x2; sigmoid rows pre-scaled by 0.5).
// h via smem broadcast. x staged via cp.async chunks, and the x-projection for
// step s+1 is software-pipelined into step s's activation-latency window.
template <bool WRITE_ALL>
__global__ void __launch_bounds__(224, 1)
lstm_layer(const float* __restrict__ in, float* __restrict__ out,
           const float* __restrict__ Wih, const float* __restrict__ Whh,
           const float* __restrict__ bih, const float* __restrict__ bhh)
{
    __shared__ __align__(16) float sh[WPB][2][2][Hn];            // [warp][parity][half][j]
    __shared__ __align__(16) float xs[WPB][2][2][CHUNK][Hn];     // [warp][buf][half][step][j]

    const int warp = threadIdx.x >> 5;
    const int lane = threadIdx.x & 31;
    const int half = lane >> 4;
    const int j    = lane & 15;
    const int b    = blockIdx.x * BPC + warp * 2 + half;
    if (b >= Bn) return;   // whole warp exits together

    // ---- weights -> registers; sigmoid-gate rows scaled by 0.5 ----
    ull wx[4][8], wh[4][8], bias[4];
    const ull halfpack = pack2(0.5f, 0.5f);
#pragma unroll
    for (int q = 0; q < 4; q++) {
        const int row = q * Hn + j;          // q: 0=i 1=f 2=g 3=o
        load8(wx[q], Wih + row * Hn);
        load8(wh[q], Whh + row * Hn);
        float bb = bih[row] + bhh[row];
        if (q != 2) {
            bb *= 0.5f;
#pragma unroll
            for (int i = 0; i < 8; i++) {
                wx[q][i] = fmul2(wx[q][i], halfpack);
                wh[q][i] = fmul2(wh[q][i], halfpack);
            }
        }
        bias[q] = pack2(bb, 0.0f);
    }

    sh[warp][0][half][j] = 0.0f;
    float c = 0.0f;

    const float* xptr = in + (size_t)b * Tn * Hn;
    float*       orow = out + (size_t)b * Tn * Hn;

    // prefetch chunk 0 (per half: 1 KB contiguous; 4 cp16/lane)
    {
        u32 s0 = (u32)__cvta_generic_to_shared(&xs[warp][0][half][0][0]);
#pragma unroll
        for (int k = 0; k < 4; k++)
            cp16(s0 + (k * 16 + j) * 16, xptr + (k * 16 + j) * 4);
        cp_commit();
    }
    __syncwarp();

    ull ax0, ax1, ax2, ax3;   // pipelined x-projection accumulators

    for (int ch = 0; ch < NCHUNK; ch++) {
        const int cur = ch & 1;
        cp_wait0();
        __syncwarp();

        // prefetch chunk ch+1 (clamped refetch at tail — harmless)
        {
            const int nch = (ch + 1 < NCHUNK) ? ch + 1 : ch;
            const float* g = xptr + nch * (CHUNK * Hn);
            u32 s0 = (u32)__cvta_generic_to_shared(&xs[warp][cur ^ 1][half][0][0]);
#pragma unroll
            for (int k = 0; k < 4; k++)
                cp16(s0 + (k * 16 + j) * 16, g + (k * 16 + j) * 4);
            cp_commit();
        }

        // prologue: x-projection for s = 0 of this chunk
        {
            ull xv[8];
            load8(xv, &xs[warp][cur][half][0][0]);
            ax0 = bias[0]; ax1 = bias[1]; ax2 = bias[2]; ax3 = bias[3];
#pragma unroll
            for (int i = 0; i < 8; i++) {
                ffma2(ax0, wx[0][i], xv[i]); ffma2(ax1, wx[1][i], xv[i]);
                ffma2(ax2, wx[2][i], xv[i]); ffma2(ax3, wx[3][i], xv[i]);
            }
        }

#pragma unroll 4
        for (int s = 0; s < CHUNK; s++) {
            const int t = ch * CHUNK + s;

            // --- critical: h-projection onto pipelined x-projection ---
            ull hp[8];
            load8(hp, &sh[warp][s & 1][half][0]);
            ull a0 = ax0, a1 = ax1, a2 = ax2, a3 = ax3;
#pragma unroll
            for (int i = 0; i < 8; i++) {
                ffma2(a0, wh[0][i], hp[i]); ffma2(a1, wh[1][i], hp[i]);
                ffma2(a2, wh[2][i], hp[i]); ffma2(a3, wh[3][i], hp[i]);
            }

            // --- off-chain: x-projection for step s+1 (fills MUFU shadow) ---
            {
                ull xv[8];
                load8(xv, &xs[warp][cur][half][(s + 1) & 15][0]);  // s=15: dummy, redone
                ax0 = bias[0]; ax1 = bias[1]; ax2 = bias[2]; ax3 = bias[3];
#pragma unroll
                for (int i = 0; i < 8; i++) {
                    ffma2(ax0, wx[0][i], xv[i]); ffma2(ax1, wx[1][i], xv[i]);
                    ffma2(ax2, wx[2][i], xv[i]); ffma2(ax3, wx[3][i], xv[i]);
                }
            }

            // --- activations ---
            float2 F0 = u2f(a0), F1 = u2f(a1), F2 = u2f(a2), F3 = u2f(a3);
            const float vi = F0.x + F0.y;   // pre-halved
            const float vf = F1.x + F1.y;   // pre-halved
            const float vg = F2.x + F2.y;
            const float vo = F3.x + F3.y;   // pre-halved

            const float si = fmaf(0.5f, tanha(vi), 0.5f);
            const float sf = fmaf(0.5f, tanha(vf), 0.5f);
            const float tg = tanha(vg);
            const float so = fmaf(0.5f, tanha(vo), 0.5f);

            c = fmaf(sf, c, si * tg);
            const float h = so * tanha(c);

            sh[warp][(s + 1) & 1][half][j] = h;
            __syncwarp();
            if (WRITE_ALL || t == Tn - 1)           // compile-time predicate
                orow[t * Hn + j] = h;
        }
    }
}

// Readout: position = last @ Wp^T + bp ; orientation = tanh(last @ Wo^T + bo)
__global__ void head_kernel(const float* __restrict__ hbuf,
                            const float* __restrict__ Wp, const float* __restrict__ bp,
                            const float* __restrict__ Wo, const float* __restrict__ bo,
                            float* __restrict__ out)
{
    int b = blockIdx.x * blockDim.x + threadIdx.x;
    if (b >= Bn) return;
    const float* h = hbuf + (size_t)b * Tn * Hn + (size_t)(Tn - 1) * Hn;
    float hv[16];
#pragma unroll
    for (int i = 0; i < 16; i++) hv[i] = h[i];

#pragma unroll
    for (int r = 0; r < 3; r++) {
        float s = bp[r];
#pragma unroll
        for (int k = 0; k < 16; k++) s += hv[k] * Wp[r * 16 + k];
        out[b * 6 + r] = s;
    }
#pragma unroll
    for (int r = 0; r < 3; r++) {
        float s = bo[r];
#pragma unroll
        for (int k = 0; k < 16; k++) s += hv[k] * Wo[r * 16 + k];
        out[b * 6 + 3 + r] = tanha(s);
    }
}

extern "C" void kernel_launch(void* const* d_in, const int* in_sizes, int n_in,
                              void* d_out, int out_size)
{
    const float* x   = (const float*)d_in[0];
    const float* Wih = (const float*)d_in[1];
    const float* Whh = (const float*)d_in[2];
    const float* bih = (const float*)d_in[3];
    const float* bhh = (const float*)d_in[4];
    const float* Wp  = (const float*)d_in[5];
    const float* bp  = (const float*)d_in[6];
    const float* Wo  = (const float*)d_in[7];
    const float* bo  = (const float*)d_in[8];
    float* out = (float*)d_out;

    float *bufA, *bufB;
    cudaGetSymbolAddress((void**)&bufA, g_bufA);
    cudaGetSymbolAddress((void**)&bufB, g_bufB);

    const float* cur = x;
    for (int l = 0; l < Ln; l++) {
        float* o = (l & 1) ? bufB : bufA;
        if (l != Ln - 1)
            lstm_layer<true><<<NBLK, 224>>>(cur, o,
                                            Wih + (size_t)l * 64 * Hn,
                                            Whh + (size_t)l * 64 * Hn,
                                            bih + (size_t)l * 64,
                                            bhh + (size_t)l * 64);
        else
            lstm_layer<false><<<NBLK, 224>>>(cur, o,
                                             Wih + (size_t)l * 64 * Hn,
                                             Whh + (size_t)l * 64 * Hn,
                                             bih + (size_t)l * 64,
                                             bhh + (size_t)l * 64);
        cur = o;
    }
    head_kernel<<<(Bn + 255) / 256, 256>>>(cur, Wp, bp, Wo, bo, out);
}